// round 5
// baseline (speedup 1.0000x reference)
#include <cuda_runtime.h>

// IF spiking neuron, T=4 timesteps, pure HBM streaming.
// Round-4: persistent one-wave grid-stride kernel.
//   grid = 148 SMs x 8 resident blocks (2048 thr/SM) -> exactly 1 wave,
//   no block relaunch bubbles, no tail wave. Inner loop unrolled x2 for
//   sustained MLP=8 across iterations.

#define T_STEPS 4
#define NUM_SMS 148
#define BLOCKS_PER_SM 8
#define TPB 256

__global__ __launch_bounds__(TPB, BLOCKS_PER_SM) void if_kernel(
    const float4* __restrict__ x,
    float4* __restrict__ out,
    const float* __restrict__ thresh_p,
    int n_vec_per_t)   // (B*C*H*W)/4 = 2,097,152
{
    const int stride = gridDim.x * blockDim.x;          // 303,104
    const float th = __ldg(thresh_p);
    const float half_th = 0.5f * th;

#pragma unroll 2
    for (int i = blockIdx.x * blockDim.x + threadIdx.x;
         i < n_vec_per_t; i += stride) {
        // 4 independent timestep loads, front-batched (x2 via unroll -> MLP 8).
        float4 x0 = __ldcs(&x[0 * (size_t)n_vec_per_t + i]);
        float4 x1 = __ldcs(&x[1 * (size_t)n_vec_per_t + i]);
        float4 x2 = __ldcs(&x[2 * (size_t)n_vec_per_t + i]);
        float4 x3 = __ldcs(&x[3 * (size_t)n_vec_per_t + i]);

        float4 m = make_float4(half_th, half_th, half_th, half_th);
        float4 s;

        m.x += x0.x; s.x = (m.x >= th) ? th : 0.0f; m.x -= s.x;
        m.y += x0.y; s.y = (m.y >= th) ? th : 0.0f; m.y -= s.y;
        m.z += x0.z; s.z = (m.z >= th) ? th : 0.0f; m.z -= s.z;
        m.w += x0.w; s.w = (m.w >= th) ? th : 0.0f; m.w -= s.w;
        __stcs(&out[0 * (size_t)n_vec_per_t + i], s);

        m.x += x1.x; s.x = (m.x >= th) ? th : 0.0f; m.x -= s.x;
        m.y += x1.y; s.y = (m.y >= th) ? th : 0.0f; m.y -= s.y;
        m.z += x1.z; s.z = (m.z >= th) ? th : 0.0f; m.z -= s.z;
        m.w += x1.w; s.w = (m.w >= th) ? th : 0.0f; m.w -= s.w;
        __stcs(&out[1 * (size_t)n_vec_per_t + i], s);

        m.x += x2.x; s.x = (m.x >= th) ? th : 0.0f; m.x -= s.x;
        m.y += x2.y; s.y = (m.y >= th) ? th : 0.0f; m.y -= s.y;
        m.z += x2.z; s.z = (m.z >= th) ? th : 0.0f; m.z -= s.z;
        m.w += x2.w; s.w = (m.w >= th) ? th : 0.0f; m.w -= s.w;
        __stcs(&out[2 * (size_t)n_vec_per_t + i], s);

        m.x += x3.x; s.x = (m.x >= th) ? th : 0.0f;
        m.y += x3.y; s.y = (m.y >= th) ? th : 0.0f;
        m.z += x3.z; s.z = (m.z >= th) ? th : 0.0f;
        m.w += x3.w; s.w = (m.w >= th) ? th : 0.0f;
        __stcs(&out[3 * (size_t)n_vec_per_t + i], s);
    }
}

extern "C" void kernel_launch(void* const* d_in, const int* in_sizes, int n_in,
                              void* d_out, int out_size) {
    const float* x = (const float*)d_in[0];
    const float* thresh = (const float*)d_in[1];

    int n_total = in_sizes[0];            // T * B * C * H * W = 33,554,432
    int n_per_t = n_total / T_STEPS;      // 8,388,608
    int n_vec_per_t = n_per_t / 4;        // 2,097,152 float4 columns

    int blocks = NUM_SMS * BLOCKS_PER_SM; // 1184 -> exactly one wave

    if_kernel<<<blocks, TPB>>>(
        (const float4*)x, (float4*)d_out, thresh, n_vec_per_t);
}

// round 6
// speedup vs baseline: 1.1074x; 1.1074x over previous
#include <cuda_runtime.h>

// IF spiking neuron, T=4 timesteps. Pure HBM streaming at ~7.45 TB/s effective
// (93% of spec) — round-1 structure reverted as fastest; TPB 256->512 micro-tune.
// Per float4 column: mem=0.5*th; for t: mem+=x_t; s=(mem>=th)?th:0; mem-=s.

#define T_STEPS 4
#define TPB 512

__global__ __launch_bounds__(TPB) void if_kernel(
    const float4* __restrict__ x,
    float4* __restrict__ out,
    const float* __restrict__ thresh_p,
    int n_vec_per_t)   // (B*C*H*W)/4 = 2,097,152
{
    int i = blockIdx.x * blockDim.x + threadIdx.x;
    if (i >= n_vec_per_t) return;

    const float th = __ldg(thresh_p);
    const float half_th = 0.5f * th;

    // Front-batch all 4 timestep loads (independent addresses -> MLP=4).
    float4 x0 = x[0 * (size_t)n_vec_per_t + i];
    float4 x1 = x[1 * (size_t)n_vec_per_t + i];
    float4 x2 = x[2 * (size_t)n_vec_per_t + i];
    float4 x3 = x[3 * (size_t)n_vec_per_t + i];

    float4 m = make_float4(half_th, half_th, half_th, half_th);
    float4 s;

    // t = 0
    m.x += x0.x; s.x = (m.x >= th) ? th : 0.0f; m.x -= s.x;
    m.y += x0.y; s.y = (m.y >= th) ? th : 0.0f; m.y -= s.y;
    m.z += x0.z; s.z = (m.z >= th) ? th : 0.0f; m.z -= s.z;
    m.w += x0.w; s.w = (m.w >= th) ? th : 0.0f; m.w -= s.w;
    out[0 * (size_t)n_vec_per_t + i] = s;

    // t = 1
    m.x += x1.x; s.x = (m.x >= th) ? th : 0.0f; m.x -= s.x;
    m.y += x1.y; s.y = (m.y >= th) ? th : 0.0f; m.y -= s.y;
    m.z += x1.z; s.z = (m.z >= th) ? th : 0.0f; m.z -= s.z;
    m.w += x1.w; s.w = (m.w >= th) ? th : 0.0f; m.w -= s.w;
    out[1 * (size_t)n_vec_per_t + i] = s;

    // t = 2
    m.x += x2.x; s.x = (m.x >= th) ? th : 0.0f; m.x -= s.x;
    m.y += x2.y; s.y = (m.y >= th) ? th : 0.0f; m.y -= s.y;
    m.z += x2.z; s.z = (m.z >= th) ? th : 0.0f; m.z -= s.z;
    m.w += x2.w; s.w = (m.w >= th) ? th : 0.0f; m.w -= s.w;
    out[2 * (size_t)n_vec_per_t + i] = s;

    // t = 3 (mem not needed afterwards)
    m.x += x3.x; s.x = (m.x >= th) ? th : 0.0f;
    m.y += x3.y; s.y = (m.y >= th) ? th : 0.0f;
    m.z += x3.z; s.z = (m.z >= th) ? th : 0.0f;
    m.w += x3.w; s.w = (m.w >= th) ? th : 0.0f;
    out[3 * (size_t)n_vec_per_t + i] = s;
}

extern "C" void kernel_launch(void* const* d_in, const int* in_sizes, int n_in,
                              void* d_out, int out_size) {
    const float* x = (const float*)d_in[0];
    const float* thresh = (const float*)d_in[1];

    int n_total = in_sizes[0];            // T * B * C * H * W = 33,554,432
    int n_per_t = n_total / T_STEPS;      // 8,388,608
    int n_vec_per_t = n_per_t / 4;        // 2,097,152 float4 columns

    int blocks = (n_vec_per_t + TPB - 1) / TPB;  // 4096

    if_kernel<<<blocks, TPB>>>(
        (const float4*)x, (float4*)d_out, thresh, n_vec_per_t);
}